// round 2
// baseline (speedup 1.0000x reference)
#include <cuda_runtime.h>

#define NB    128
#define CIN   8
#define HIN   128
#define WIN   128
#define COUT  64
#define HO    126
#define WO    126
#define PHN   31
#define PWN   31
#define NG    16
#define CPG   4

typedef unsigned long long u64;

__device__ float  g_smax[(size_t)NB * COUT * PHN * PWN];
__device__ float  g_smin[(size_t)NB * COUT * PHN * PWN];
__device__ float2 g_partial[32 * NB * NG];
__device__ float2 g_stats[NB * NG];

// ---- packed f32x2 helpers (sm_100+) ----
__device__ __forceinline__ u64 pk2(float lo, float hi) {
    u64 r; asm("mov.b64 %0, {%1, %2};" : "=l"(r) : "f"(lo), "f"(hi)); return r;
}
__device__ __forceinline__ void upk2(float& lo, float& hi, u64 p) {
    asm("mov.b64 {%0, %1}, %2;" : "=f"(lo), "=f"(hi) : "l"(p));
}
__device__ __forceinline__ void ffma2(u64& d, u64 a, u64 b) {
    asm("fma.rn.f32x2 %0, %1, %2, %0;" : "+l"(d) : "l"(a), "l"(b));
}
__device__ __forceinline__ void fadd2(u64& d, u64 a) {
    asm("add.rn.f32x2 %0, %1, %0;" : "+l"(d) : "l"(a));
}

// ---------------------------------------------------------------------------
// Pass 1: conv + bias; per-window max/min; per-(b,g) partial stats.
// Grid: (32 row-groups, 128 batches, 2 channel-halves), block = 256.
// Thread t: wx = t&31 (window col), cb = t>>5 -> 4 channels z*32+cb*4..+3.
// A warp (fixed cb) owns exactly one GroupNorm group g = z*8+cb.
// ---------------------------------------------------------------------------
__global__ __launch_bounds__(256, 2) void conv_pass1(const float* __restrict__ x,
                                                     const float* __restrict__ w,
                                                     const float* __restrict__ bias)
{
    const int pr = blockIdx.x;          // 0..31
    const int b  = blockIdx.y;
    const int z  = blockIdx.z;          // channel half
    const int t  = threadIdx.x;

    __shared__ float  xs[CIN][6][132];  // 6 input rows, 128 cols + 4 zero pad
    __shared__ float2 wsm[72][32];      // [cin*9+ky*3+kx][cl] duplicated (w,w)
    __shared__ float  bsm[32];

    // weights for this half: global layout [co][cin][ky][kx]
    for (int i = t; i < 72 * 32; i += 256) {
        int cl = i & 31, k = i >> 5;
        float v = w[(z * 32 + cl) * 72 + k];
        wsm[k][cl] = make_float2(v, v);
    }
    if (t < 32) bsm[t] = bias[z * 32 + t];

    const int h0 = pr * 4;
    for (int i = t; i < CIN * 6 * 32; i += 256) {
        int c4  = i & 31;
        int rr  = (i >> 5) % 6;
        int cin = i / (6 * 32);
        int h   = h0 + rr;
        float4 v = make_float4(0.f, 0.f, 0.f, 0.f);
        if (h < HIN)
            v = *(const float4*)&x[(((size_t)b * CIN + cin) * HIN + h) * WIN + c4 * 4];
        *(float4*)&xs[cin][rr][c4 * 4] = v;
    }
    if (t < CIN * 6) {
        int rr = t % 6, cin = t / 6;
        *(float4*)&xs[cin][rr][128] = make_float4(0.f, 0.f, 0.f, 0.f);
    }
    __syncthreads();

    const int wx   = t & 31;
    const int cb   = t >> 5;
    const int col0 = wx * 4;
    const int R    = (pr == 31) ? 2 : 4;

    float wmax[4], wmin[4];
#pragma unroll
    for (int j = 0; j < 4; j++) { wmax[j] = -1e30f; wmin[j] = 1e30f; }
    u64 s2 = 0ULL, q2 = 0ULL;          // packed (even-col, odd-col) sums

#pragma unroll 1
    for (int rr = 0; rr < R; rr += 2) {
        u64 acc[2][4][2];
#pragma unroll
        for (int r2 = 0; r2 < 2; r2++)
#pragma unroll
            for (int j = 0; j < 4; j++) { acc[r2][j][0] = 0ULL; acc[r2][j][1] = 0ULL; }

#pragma unroll
        for (int cin = 0; cin < CIN; cin++) {
#pragma unroll
            for (int ky = 0; ky < 3; ky++) {
                const u64* w0p = (const u64*)&wsm[cin * 9 + ky * 3 + 0][cb * 4];
                const u64* w1p = (const u64*)&wsm[cin * 9 + ky * 3 + 1][cb * 4];
                const u64* w2p = (const u64*)&wsm[cin * 9 + ky * 3 + 2][cb * 4];
                u64 W0[4], W1[4], W2[4];
#pragma unroll
                for (int j = 0; j < 4; j++) { W0[j] = w0p[j]; W1[j] = w1p[j]; W2[j] = w2p[j]; }

#pragma unroll
                for (int r2 = 0; r2 < 2; r2++) {
                    const float* xr = &xs[cin][rr + r2 + ky][col0];
                    float4 xa = *(const float4*)xr;
                    float2 xb = *(const float2*)(xr + 4);
                    u64 p01 = pk2(xa.x, xa.y);
                    u64 p12 = pk2(xa.y, xa.z);
                    u64 p23 = pk2(xa.z, xa.w);
                    u64 p34 = pk2(xa.w, xb.x);
                    u64 p45 = pk2(xb.x, xb.y);
#pragma unroll
                    for (int j = 0; j < 4; j++) {
                        ffma2(acc[r2][j][0], W0[j], p01);
                        ffma2(acc[r2][j][0], W1[j], p12);
                        ffma2(acc[r2][j][0], W2[j], p23);
                        ffma2(acc[r2][j][1], W0[j], p23);
                        ffma2(acc[r2][j][1], W1[j], p34);
                        ffma2(acc[r2][j][1], W2[j], p45);
                    }
                }
            }
        }

        // epilogue: bias, stats, window min/max for rows rr, rr+1
#pragma unroll
        for (int r2 = 0; r2 < 2; r2++) {
#pragma unroll
            for (int j = 0; j < 4; j++) {
                float bb = bsm[cb * 4 + j];
                u64 bp = pk2(bb, bb);
                u64 a01 = acc[r2][j][0]; fadd2(a01, bp);
                u64 a23 = acc[r2][j][1]; fadd2(a23, bp);
                float v0, v1, v2, v3;
                upk2(v0, v1, a01);
                upk2(v2, v3, a23);
                if (wx < 31) {
                    fadd2(s2, a01); fadd2(s2, a23);
                    ffma2(q2, a01, a01); ffma2(q2, a23, a23);
                    wmax[j] = fmaxf(wmax[j], fmaxf(fmaxf(v0, v1), fmaxf(v2, v3)));
                    wmin[j] = fminf(wmin[j], fminf(fminf(v0, v1), fminf(v2, v3)));
                } else {
                    // cols 124,125 valid for stats only
                    fadd2(s2, a01); ffma2(q2, a01, a01);
                }
            }
        }
    }

    // pooled window raw max/min
    if (pr < 31 && wx < 31) {
#pragma unroll
        for (int j = 0; j < 4; j++) {
            int co = z * 32 + cb * 4 + j;
            size_t o = (((size_t)b * COUT + co) * PHN + pr) * PWN + wx;
            g_smax[o] = wmax[j];
            g_smin[o] = wmin[j];
        }
    }

    // warp-level stats reduction; warp cb exclusively owns group z*8+cb
    float sl, sh, ql, qh;
    upk2(sl, sh, s2);
    upk2(ql, qh, q2);
    float s = sl + sh, q = ql + qh;
#pragma unroll
    for (int o = 16; o > 0; o >>= 1) {
        s += __shfl_down_sync(0xffffffffu, s, o);
        q += __shfl_down_sync(0xffffffffu, q, o);
    }
    if (wx == 0)
        g_partial[(pr * NB + b) * NG + z * 8 + cb] = make_float2(s, q);
}

// ---------------------------------------------------------------------------
// Pass 2: fold 32 row-group partials into mean/rstd per (b, g).
// ---------------------------------------------------------------------------
__global__ void stats_pass2()
{
    int idx = blockIdx.x * 256 + threadIdx.x;   // b*16+g
    if (idx >= NB * NG) return;
    float s = 0.f, q = 0.f;
    for (int pr = 0; pr < 32; pr++) {
        float2 p = g_partial[pr * (NB * NG) + idx];
        s += p.x; q += p.y;
    }
    const float inv = 1.f / (float)(CPG * HO * WO);
    float mean = s * inv;
    float var  = q * inv - mean * mean;
    g_stats[idx] = make_float2(mean, rsqrtf(var + 1e-5f));
}

// ---------------------------------------------------------------------------
// Pass 3: per output element, affine-of-max/min + clamp.
// ---------------------------------------------------------------------------
__global__ void apply_pass3(const float* __restrict__ gnw,
                            const float* __restrict__ gnb,
                            const float* __restrict__ scale,
                            float* __restrict__ out, int n)
{
    int idx = blockIdx.x * 256 + threadIdx.x;
    if (idx >= n) return;
    int tmp = idx / PWN;
    tmp /= PHN;
    int c = tmp % COUT;
    int b = tmp / COUT;

    float2 st = g_stats[b * NG + (c >> 2)];
    float gw = gnw[c], sc = scale[c];
    float A  = st.y * gw * sc;
    float Bt = (gnb[c] - st.x * st.y * gw) * sc;

    float y = (A >= 0.f) ? g_smax[idx] : g_smin[idx];
    float v = fmaf(A, y, Bt);
    out[idx] = fminf(fmaxf(v, 0.f), 1.f);
}

// ---------------------------------------------------------------------------
extern "C" void kernel_launch(void* const* d_in, const int* in_sizes, int n_in,
                              void* d_out, int out_size)
{
    const float* x     = (const float*)d_in[0];
    const float* w     = (const float*)d_in[1];
    const float* bias  = (const float*)d_in[2];
    const float* gnw   = (const float*)d_in[3];
    const float* gnb   = (const float*)d_in[4];
    const float* scale = (const float*)d_in[5];
    float* out = (float*)d_out;

    dim3 g1(32, NB, 2);
    conv_pass1<<<g1, 256>>>(x, w, bias);
    stats_pass2<<<(NB * NG + 255) / 256, 256>>>();
    int n = NB * COUT * PHN * PWN;
    apply_pass3<<<(n + 255) / 256, 256>>>(gnw, gnb, scale, out, n);
}

// round 3
// speedup vs baseline: 1.8617x; 1.8617x over previous
#include <cuda_runtime.h>

#define NB    128
#define CIN   8
#define HIN   128
#define WIN   128
#define COUT  64
#define HO    126
#define WO    126
#define PHN   31
#define PWN   31
#define NG    16
#define CPG   4

__device__ float  g_smax[(size_t)NB * COUT * PHN * PWN];
__device__ float  g_smin[(size_t)NB * COUT * PHN * PWN];
__device__ float2 g_partial[32 * NB * NG];
__device__ float2 g_stats[NB * NG];

// ---------------------------------------------------------------------------
// Pass 1: conv + bias; per-window max/min; per-(b,g) partial stats.
// Grid: (32 row-groups, 128 batches, 2 channel-halves), block = 256.
// Thread t: wx = t&31 (4-col window), cb = t>>5 -> channels z*32+cb*4..+3.
// Warp (fixed cb) owns exactly GroupNorm group g = z*8+cb.
// ---------------------------------------------------------------------------
__global__ __launch_bounds__(256, 2) void conv_pass1(const float* __restrict__ x,
                                                     const float* __restrict__ w,
                                                     const float* __restrict__ bias)
{
    const int pr = blockIdx.x;          // 0..31
    const int b  = blockIdx.y;
    const int z  = blockIdx.z;          // channel half
    const int t  = threadIdx.x;

    __shared__ float xs[CIN][6][132];   // 6 input rows, 128 cols + 4 zero pad
    __shared__ float wsm[72][32];       // [cin*9+ky*3+kx][cl]  (half's channels)
    __shared__ float bsm[32];

    // weights for this half: global layout [co][cin][ky][kx]
    for (int i = t; i < 72 * 32; i += 256) {
        int cl = i & 31, k = i >> 5;
        wsm[k][cl] = w[(z * 32 + cl) * 72 + k];
    }
    if (t < 32) bsm[t] = bias[z * 32 + t];

    const int h0 = pr * 4;
    for (int i = t; i < CIN * 6 * 32; i += 256) {
        int c4  = i & 31;
        int rr  = (i >> 5) % 6;
        int cin = i / (6 * 32);
        int h   = h0 + rr;
        float4 v = make_float4(0.f, 0.f, 0.f, 0.f);
        if (h < HIN)
            v = *(const float4*)&x[(((size_t)b * CIN + cin) * HIN + h) * WIN + c4 * 4];
        *(float4*)&xs[cin][rr][c4 * 4] = v;
    }
    if (t < CIN * 6) {
        int rr = t % 6, cin = t / 6;
        *(float4*)&xs[cin][rr][128] = make_float4(0.f, 0.f, 0.f, 0.f);
    }
    __syncthreads();

    const int wx   = t & 31;
    const int cb   = t >> 5;
    const int col0 = wx * 4;
    const int R    = (pr == 31) ? 2 : 4;

    float wmax[4], wmin[4];
#pragma unroll
    for (int j = 0; j < 4; j++) { wmax[j] = -1e30f; wmin[j] = 1e30f; }
    float s = 0.f, q = 0.f;

#pragma unroll 1
    for (int r = 0; r < R; r++) {
        float acc[4][4];
#pragma unroll
        for (int j = 0; j < 4; j++)
#pragma unroll
            for (int c = 0; c < 4; c++) acc[j][c] = 0.f;

#pragma unroll
        for (int cin = 0; cin < CIN; cin++) {
#pragma unroll
            for (int ky = 0; ky < 3; ky++) {
                const float* xr = &xs[cin][r + ky][col0];
                float4 xa = *(const float4*)xr;
                float2 xb = *(const float2*)(xr + 4);
                float xv0 = xa.x, xv1 = xa.y, xv2 = xa.z;
                float xv3 = xa.w, xv4 = xb.x, xv5 = xb.y;
                float4 W0 = *(const float4*)&wsm[cin * 9 + ky * 3 + 0][cb * 4];
                float4 W1 = *(const float4*)&wsm[cin * 9 + ky * 3 + 1][cb * 4];
                float4 W2 = *(const float4*)&wsm[cin * 9 + ky * 3 + 2][cb * 4];
                const float* w0 = (const float*)&W0;
                const float* w1 = (const float*)&W1;
                const float* w2 = (const float*)&W2;
#pragma unroll
                for (int j = 0; j < 4; j++) {
                    acc[j][0] = fmaf(w0[j], xv0, fmaf(w1[j], xv1, fmaf(w2[j], xv2, acc[j][0])));
                    acc[j][1] = fmaf(w0[j], xv1, fmaf(w1[j], xv2, fmaf(w2[j], xv3, acc[j][1])));
                    acc[j][2] = fmaf(w0[j], xv2, fmaf(w1[j], xv3, fmaf(w2[j], xv4, acc[j][2])));
                    acc[j][3] = fmaf(w0[j], xv3, fmaf(w1[j], xv4, fmaf(w2[j], xv5, acc[j][3])));
                }
            }
        }

        // epilogue: bias, stats, window min/max
#pragma unroll
        for (int j = 0; j < 4; j++) {
            float bb = bsm[cb * 4 + j];
            float v0 = acc[j][0] + bb, v1 = acc[j][1] + bb;
            float v2 = acc[j][2] + bb, v3 = acc[j][3] + bb;
            if (wx < 31) {
                s += (v0 + v1) + (v2 + v3);
                q += (v0 * v0 + v1 * v1) + (v2 * v2 + v3 * v3);
                wmax[j] = fmaxf(wmax[j], fmaxf(fmaxf(v0, v1), fmaxf(v2, v3)));
                wmin[j] = fminf(wmin[j], fminf(fminf(v0, v1), fminf(v2, v3)));
            } else {
                s += v0 + v1;               // cols 124,125 valid for stats only
                q += v0 * v0 + v1 * v1;
            }
        }
    }

    // pooled window raw max/min
    if (pr < 31 && wx < 31) {
#pragma unroll
        for (int j = 0; j < 4; j++) {
            int co = z * 32 + cb * 4 + j;
            size_t o = (((size_t)b * COUT + co) * PHN + pr) * PWN + wx;
            g_smax[o] = wmax[j];
            g_smin[o] = wmin[j];
        }
    }

    // warp-level stats reduction; warp cb exclusively owns group z*8+cb
#pragma unroll
    for (int o = 16; o > 0; o >>= 1) {
        s += __shfl_down_sync(0xffffffffu, s, o);
        q += __shfl_down_sync(0xffffffffu, q, o);
    }
    if (wx == 0)
        g_partial[(pr * NB + b) * NG + z * 8 + cb] = make_float2(s, q);
}

// ---------------------------------------------------------------------------
// Pass 2: fold 32 row-group partials into mean/rstd per (b, g).
// ---------------------------------------------------------------------------
__global__ void stats_pass2()
{
    int idx = blockIdx.x * 256 + threadIdx.x;   // b*16+g
    if (idx >= NB * NG) return;
    float s = 0.f, q = 0.f;
    for (int pr = 0; pr < 32; pr++) {
        float2 p = g_partial[pr * (NB * NG) + idx];
        s += p.x; q += p.y;
    }
    const float inv = 1.f / (float)(CPG * HO * WO);
    float mean = s * inv;
    float var  = q * inv - mean * mean;
    g_stats[idx] = make_float2(mean, rsqrtf(var + 1e-5f));
}

// ---------------------------------------------------------------------------
// Pass 3: per output element, affine-of-max/min + clamp.
// ---------------------------------------------------------------------------
__global__ void apply_pass3(const float* __restrict__ gnw,
                            const float* __restrict__ gnb,
                            const float* __restrict__ scale,
                            float* __restrict__ out, int n)
{
    int idx = blockIdx.x * 256 + threadIdx.x;
    if (idx >= n) return;
    int tmp = idx / PWN;
    tmp /= PHN;
    int c = tmp % COUT;
    int b = tmp / COUT;

    float2 st = g_stats[b * NG + (c >> 2)];
    float gw = gnw[c], sc = scale[c];
    float A  = st.y * gw * sc;
    float Bt = (gnb[c] - st.x * st.y * gw) * sc;

    float y = (A >= 0.f) ? g_smax[idx] : g_smin[idx];
    float v = fmaf(A, y, Bt);
    out[idx] = fminf(fmaxf(v, 0.f), 1.f);
}

// ---------------------------------------------------------------------------
extern "C" void kernel_launch(void* const* d_in, const int* in_sizes, int n_in,
                              void* d_out, int out_size)
{
    const float* x     = (const float*)d_in[0];
    const float* w     = (const float*)d_in[1];
    const float* bias  = (const float*)d_in[2];
    const float* gnw   = (const float*)d_in[3];
    const float* gnb   = (const float*)d_in[4];
    const float* scale = (const float*)d_in[5];
    float* out = (float*)d_out;

    dim3 g1(32, NB, 2);
    conv_pass1<<<g1, 256>>>(x, w, bias);
    stats_pass2<<<(NB * NG + 255) / 256, 256>>>();
    int n = NB * COUT * PHN * PWN;
    apply_pass3<<<(n + 255) / 256, 256>>>(gnw, gnb, scale, out, n);
}